// round 6
// baseline (speedup 1.0000x reference)
#include <cuda_runtime.h>
#include <math.h>
#include <cstdint>

#define Hh    64
#define GATES 256
#define OBS_  20
#define MB    64     // batch per CTA
#define NT    512    // 16 warps

typedef unsigned long long ULL;

// ---- SMEM layout (floats) ----
#define OFF_W     0                         // [128][256] permuted (slot = ty*8+g*2+d)
#define OFF_X0    (OFF_W + 128*GATES)       // [64][64] x buffer 0
#define OFF_X1    (OFF_X0 + 64*MB)          // [64][64] x buffer 1
#define OFF_H0    (OFF_X1 + 64*MB)          // [64][64] h buffer 0
#define OFF_H1    (OFF_H0 + 64*MB)          // [64][64] h buffer 1
#define OFF_BIAS  (OFF_H1 + 64*MB)          // [256] permuted
#define OFF_WE    (OFF_BIAS + GATES)        // [2][64]
#define OFF_BE    (OFF_WE + 128)            // [64]
#define OFF_WFC   (OFF_BE + 64)             // [2][64]
#define OFF_BFC   (OFF_WFC + 128)           // [2] +2 pad
#define OFF_OBS   (OFF_BFC + 4)             // [40][64]
#define SMEM_FLOATS (OFF_OBS + OBS_*2*MB)
#define SMEM_BYTES  (SMEM_FLOATS * 4)

#define FMA_F32X2(d, a, b, c_) \
    asm("fma.rn.f32x2 %0, %1, %2, %3;" : "=l"(d) : "l"(a), "l"(b), "l"(c_))
#define PACK_DUP(out, v) \
    asm("mov.b64 %0, {%1, %1};" : "=l"(out) : "r"(v))
#define UNPACK2(lo, hi, in) \
    asm("mov.b64 {%0, %1}, %2;" : "=r"(lo), "=r"(hi) : "l"(in))

__device__ __forceinline__ float sigf(float x) {
    return __fdividef(1.0f, 1.0f + __expf(-x));
}
__device__ __forceinline__ float tanh_(float x) {
    float a = fabsf(x);
    float e = __expf(2.0f * a);                 // may be +inf, fine
    float t = 1.0f - __fdividef(2.0f, e + 1.0f);
    return copysignf(t, x);
}

__global__ void __launch_bounds__(NT, 1)
vanilla_lstm_kernel(const float* __restrict__ obs,
                    const float* __restrict__ W_emb,  const float* __restrict__ b_emb,
                    const float* __restrict__ Wih_e,  const float* __restrict__ Whh_e,
                    const float* __restrict__ bih_e,  const float* __restrict__ bhh_e,
                    const float* __restrict__ Wih_d,  const float* __restrict__ Whh_d,
                    const float* __restrict__ bih_d,  const float* __restrict__ bhh_d,
                    const float* __restrict__ W_fc,   const float* __restrict__ b_fc,
                    float* __restrict__ out, int pred_len)
{
    extern __shared__ float sm[];
    float* sW    = sm + OFF_W;
    float* sBias = sm + OFF_BIAS;
    float* sWe   = sm + OFF_WE;
    float* sBe   = sm + OFF_BE;
    float* sWfc  = sm + OFF_WFC;
    float* sBfc  = sm + OFF_BFC;
    float* sObsF = sm + OFF_OBS;
    float* sXb[2] = { sm + OFF_X0, sm + OFF_X1 };
    float* sHb[2] = { sm + OFF_H0, sm + OFF_H1 };

    const int tid = threadIdx.x;
    const int tx  = tid & 15;          // batch pair within 32-stream (2 cols)
    const int ty  = tid >> 4;          // hidden pair (0..31)
    const int b0  = blockIdx.x * MB;

    // ---- stage small params ----
    if (tid < 128) sWe[tid] = W_emb[(tid & 63) * 2 + (tid >> 6)];
    if (tid < 64)  sBe[tid] = b_emb[tid];
    if (tid < 128) sWfc[tid] = W_fc[tid];
    if (tid < 2)   sBfc[tid] = b_fc[tid];

    // obs cache: sObs[r*64 + b]
    for (int i = tid; i < MB * OBS_ * 2; i += NT) {
        int b = i / (OBS_ * 2);
        int r = i % (OBS_ * 2);
        sObsF[r * MB + b] = obs[(size_t)(b0 + b) * (OBS_ * 2) + r];
    }
    // zero h buffer 0
    for (int i = tid; i < 64 * MB; i += NT) sHb[0][i] = 0.0f;

    // ---- stage weights (permuted): row=g*64+ty2*2+d -> slot=ty2*8+g*2+d ----
    auto stageW = [&](const float* Wih, const float* Whh,
                      const float* bih, const float* bhh) {
        for (int i = tid; i < GATES * 64; i += NT) {
            int row = i >> 6, k = i & 63;
            int g = row >> 6, hidx = row & 63;
            int slot = (hidx >> 1) * 8 + g * 2 + (hidx & 1);
            sW[k * GATES + slot]        = Wih[i];
            sW[(64 + k) * GATES + slot] = Whh[i];
        }
        for (int row = tid; row < GATES; row += NT) {
            int g = row >> 6, hidx = row & 63;
            sBias[(hidx >> 1) * 8 + g * 2 + (hidx & 1)] = bih[row] + bhh[row];
        }
    };
    stageW(Wih_e, Whh_e, bih_e, bhh_e);

    // ---- embed obs step tt into x buffer buf ----
    auto embed_obs = [&](int tt, int buf) {
        int b = tid & 63, k0 = (tid >> 6) * 8;
        float p0 = sObsF[(2 * tt) * MB + b], p1 = sObsF[(2 * tt + 1) * MB + b];
        float* dst = sXb[buf];
        #pragma unroll
        for (int j = 0; j < 8; j++) {
            int e = k0 + j;
            float v = fmaf(p0, sWe[e], fmaf(p1, sWe[64 + e], sBe[e]));
            dst[e * MB + b] = fmaxf(v, 0.0f);
        }
    };

    // ---- fused FC + (optional) embed of pred; reads sH[cur], writes sX[cur] ----
    auto fc_embed = [&](int cur, int pi, bool emb) {
        int b = tid & 63;
        float p0 = sBfc[0], p1 = sBfc[1];
        const float* hcol = sHb[cur] + b;
        #pragma unroll 8
        for (int r = 0; r < 64; r++) {
            float h = hcol[r * MB];
            p0 = fmaf(h, sWfc[r],      p0);
            p1 = fmaf(h, sWfc[64 + r], p1);
        }
        if (tid < MB) {
            size_t o = ((size_t)(b0 + b) * pred_len + pi) * 2;
            *(float2*)(out + o) = make_float2(p0, p1);
        }
        if (emb) {
            int k0 = (tid >> 6) * 8;
            float* dst = sXb[cur];
            #pragma unroll
            for (int j = 0; j < 8; j++) {
                int e = k0 + j;
                float v = fmaf(p0, sWe[e], fmaf(p1, sWe[64 + e], sBe[e]));
                dst[e * MB + b] = fmaxf(v, 0.0f);
            }
        }
    };

    // ---- GEMM for one 32-batch stream ----
    auto gemm_stream = [&](int cur, int cb, ULL acc[4][2]) {
        #pragma unroll
        for (int g = 0; g < 4; g++) {
            ULL bp = *(const ULL*)(sBias + ty * 8 + g * 2);
            acc[g][0] = bp; acc[g][1] = bp;
        }
        const float* xp = sXb[cur] + cb;
        const float* wp = sW + ty * 8;
        #pragma unroll 8
        for (int k = 0; k < 64; k++) {
            float2 xv = *(const float2*)xp; xp += MB;
            ULL x0, x1;
            PACK_DUP(x0, __float_as_uint(xv.x));
            PACK_DUP(x1, __float_as_uint(xv.y));
            float4 w01 = *(const float4*)wp;
            float4 w23 = *(const float4*)(wp + 4); wp += GATES;
            ULL wq0 = *(ULL*)&w01.x, wq1 = *(ULL*)&w01.z;
            ULL wq2 = *(ULL*)&w23.x, wq3 = *(ULL*)&w23.z;
            FMA_F32X2(acc[0][0], wq0, x0, acc[0][0]);
            FMA_F32X2(acc[0][1], wq0, x1, acc[0][1]);
            FMA_F32X2(acc[1][0], wq1, x0, acc[1][0]);
            FMA_F32X2(acc[1][1], wq1, x1, acc[1][1]);
            FMA_F32X2(acc[2][0], wq2, x0, acc[2][0]);
            FMA_F32X2(acc[2][1], wq2, x1, acc[2][1]);
            FMA_F32X2(acc[3][0], wq3, x0, acc[3][0]);
            FMA_F32X2(acc[3][1], wq3, x1, acc[3][1]);
        }
        const float* hp = sHb[cur] + cb;
        #pragma unroll 8
        for (int k = 0; k < 64; k++) {
            float2 xv = *(const float2*)hp; hp += MB;
            ULL x0, x1;
            PACK_DUP(x0, __float_as_uint(xv.x));
            PACK_DUP(x1, __float_as_uint(xv.y));
            float4 w01 = *(const float4*)wp;
            float4 w23 = *(const float4*)(wp + 4); wp += GATES;
            ULL wq0 = *(ULL*)&w01.x, wq1 = *(ULL*)&w01.z;
            ULL wq2 = *(ULL*)&w23.x, wq3 = *(ULL*)&w23.z;
            FMA_F32X2(acc[0][0], wq0, x0, acc[0][0]);
            FMA_F32X2(acc[0][1], wq0, x1, acc[0][1]);
            FMA_F32X2(acc[1][0], wq1, x0, acc[1][0]);
            FMA_F32X2(acc[1][1], wq1, x1, acc[1][1]);
            FMA_F32X2(acc[2][0], wq2, x0, acc[2][0]);
            FMA_F32X2(acc[2][1], wq2, x1, acc[2][1]);
            FMA_F32X2(acc[3][0], wq3, x0, acc[3][0]);
            FMA_F32X2(acc[3][1], wq3, x1, acc[3][1]);
        }
    };

    // ---- epilogue for one stream: activations + h store (to next buffer) ----
    auto epi_stream = [&](ULL acc[4][2], float cS[2][2], int nxt, int cb) {
        float hv[2][2];
        #pragma unroll
        for (int b = 0; b < 2; b++) {
            unsigned i0, i1, f0, f1, g0, g1, o0, o1;
            UNPACK2(i0, i1, acc[0][b]);
            UNPACK2(f0, f1, acc[1][b]);
            UNPACK2(g0, g1, acc[2][b]);
            UNPACK2(o0, o1, acc[3][b]);
            {
                float ig = sigf(__uint_as_float(i0));
                float fg = sigf(__uint_as_float(f0));
                float gg = tanh_(__uint_as_float(g0));
                float og = sigf(__uint_as_float(o0));
                float cn = fmaf(fg, cS[0][b], ig * gg);
                cS[0][b] = cn;
                hv[0][b] = og * tanh_(cn);
            }
            {
                float ig = sigf(__uint_as_float(i1));
                float fg = sigf(__uint_as_float(f1));
                float gg = tanh_(__uint_as_float(g1));
                float og = sigf(__uint_as_float(o1));
                float cn = fmaf(fg, cS[1][b], ig * gg);
                cS[1][b] = cn;
                hv[1][b] = og * tanh_(cn);
            }
        }
        float* dst = sHb[nxt];
        *(float2*)(dst + (2 * ty + 0) * MB + cb) = make_float2(hv[0][0], hv[0][1]);
        *(float2*)(dst + (2 * ty + 1) * MB + cb) = make_float2(hv[1][0], hv[1][1]);
    };

    __syncthreads();
    embed_obs(0, 0);

    float cA[2][2] = {{0.f,0.f},{0.f,0.f}};
    float cB[2][2] = {{0.f,0.f},{0.f,0.f}};

    int cur = 0;
    const int TOT = OBS_ + pred_len;
    for (int t = 0; t < TOT; t++) {
        __syncthreads();                               // prev writes visible
        if (t == OBS_) { stageW(Wih_d, Whh_d, bih_d, bhh_d); __syncthreads(); }
        if (t >= OBS_ + 1) { fc_embed(cur, t - OBS_ - 1, true); __syncthreads(); }

        ULL accA[4][2], accB[4][2];
        gemm_stream(cur, tx * 2,      accA);
        gemm_stream(cur, 32 + tx * 2, accB);

        int nxt = cur ^ 1;
        epi_stream(accA, cA, nxt, tx * 2);
        epi_stream(accB, cB, nxt, 32 + tx * 2);

        if (t < OBS_) embed_obs((t + 1 < OBS_) ? t + 1 : OBS_ - 1, nxt);
        cur = nxt;
    }
    __syncthreads();
    fc_embed(cur, pred_len - 1, false);
}

extern "C" void kernel_launch(void* const* d_in, const int* in_sizes, int n_in,
                              void* d_out, int out_size)
{
    const float* obs   = (const float*)d_in[0];
    const float* W_emb = (const float*)d_in[1];
    const float* b_emb = (const float*)d_in[2];
    const float* Wih_e = (const float*)d_in[3];
    const float* Whh_e = (const float*)d_in[4];
    const float* bih_e = (const float*)d_in[5];
    const float* bhh_e = (const float*)d_in[6];
    const float* Wih_d = (const float*)d_in[7];
    const float* Whh_d = (const float*)d_in[8];
    const float* bih_d = (const float*)d_in[9];
    const float* bhh_d = (const float*)d_in[10];
    const float* W_fc  = (const float*)d_in[11];
    const float* b_fc  = (const float*)d_in[12];
    float* out = (float*)d_out;

    int B = in_sizes[0] / (OBS_ * 2);
    int pred_len = out_size / (B * 2);

    cudaFuncSetAttribute(vanilla_lstm_kernel,
                         cudaFuncAttributeMaxDynamicSharedMemorySize, SMEM_BYTES);

    int grid = B / MB;
    vanilla_lstm_kernel<<<grid, NT, SMEM_BYTES>>>(
        obs, W_emb, b_emb, Wih_e, Whh_e, bih_e, bhh_e,
        Wih_d, Whh_d, bih_d, bhh_d, W_fc, b_fc, out, pred_len);
}

// round 7
// speedup vs baseline: 1.1963x; 1.1963x over previous
#include <cuda_runtime.h>
#include <math.h>
#include <cstdint>

#define GATES 256
#define OBS_  20
#define MB    64
#define NT    512

typedef unsigned long long ULL;

// ---- SMEM layout (floats) ----
#define OFF_W     0                         // [128][256] permuted (slot = ty*8+g*2+d)
#define OFF_X0    (OFF_W + 128*GATES)       // [64][64]
#define OFF_X1    (OFF_X0 + 64*MB)
#define OFF_H0    (OFF_X1 + 64*MB)
#define OFF_H1    (OFF_H0 + 64*MB)
#define OFF_BIAS  (OFF_H1 + 64*MB)          // [256] permuted
#define OFF_WE    (OFF_BIAS + GATES)        // [2][64]
#define OFF_BE    (OFF_WE + 128)
#define OFF_WFC   (OFF_BE + 64)             // [2][64]
#define OFF_BFC   (OFF_WFC + 128)           // [2]+pad
#define OFF_OBS   (OFF_BFC + 4)             // [40][64]
#define SMEM_FLOATS (OFF_OBS + OBS_*2*MB)
#define SMEM_BYTES  (SMEM_FLOATS * 4)

#define FMA_F32X2(d, a, b, c_) \
    asm("fma.rn.f32x2 %0, %1, %2, %3;" : "=l"(d) : "l"(a), "l"(b), "l"(c_))
#define PACK_DUP(out, v) \
    asm("mov.b64 %0, {%1, %1};" : "=l"(out) : "r"(v))
#define UNPACK2(lo, hi, in) \
    asm("mov.b64 {%0, %1}, %2;" : "=r"(lo), "=r"(hi) : "l"(in))

__device__ __forceinline__ float sigf(float x) {
    return __fdividef(1.0f, 1.0f + __expf(-x));
}
__device__ __forceinline__ float tanh_(float x) {
    float a = fabsf(x);
    float e = __expf(2.0f * a);
    float t = 1.0f - __fdividef(2.0f, e + 1.0f);
    return copysignf(t, x);
}

__global__ void __launch_bounds__(NT, 1)
vanilla_lstm_kernel(const float* __restrict__ obs,
                    const float* __restrict__ W_emb,  const float* __restrict__ b_emb,
                    const float* __restrict__ Wih_e,  const float* __restrict__ Whh_e,
                    const float* __restrict__ bih_e,  const float* __restrict__ bhh_e,
                    const float* __restrict__ Wih_d,  const float* __restrict__ Whh_d,
                    const float* __restrict__ bih_d,  const float* __restrict__ bhh_d,
                    const float* __restrict__ W_fc,   const float* __restrict__ b_fc,
                    float* __restrict__ out, int pred_len)
{
    extern __shared__ float sm[];
    float* sW    = sm + OFF_W;
    float* sBias = sm + OFF_BIAS;
    float* sWe   = sm + OFF_WE;
    float* sBe   = sm + OFF_BE;
    float* sWfc  = sm + OFF_WFC;
    float* sBfc  = sm + OFF_BFC;
    float* sObsF = sm + OFF_OBS;
    float* xb[2] = { sm + OFF_X0, sm + OFF_X1 };
    float* hb[2] = { sm + OFF_H0, sm + OFF_H1 };

    const int tid = threadIdx.x;
    const int tx  = tid & 15;          // 4 batch cols
    const int ty  = (tid >> 4) & 31;   // hidden pair
    const int b0  = blockIdx.x * MB;

    // ---- stage small params ----
    if (tid < 128) sWe[tid] = W_emb[(tid & 63) * 2 + (tid >> 6)];
    if (tid < 64)  sBe[tid] = b_emb[tid];
    if (tid < 128) sWfc[tid] = W_fc[tid];
    if (tid < 2)   sBfc[tid] = b_fc[tid];

    for (int i = tid; i < MB * OBS_ * 2; i += NT) {
        int b = i / (OBS_ * 2);
        int r = i % (OBS_ * 2);
        sObsF[r * MB + b] = obs[(size_t)(b0 + b) * (OBS_ * 2) + r];
    }
    for (int i = tid; i < 64 * MB; i += NT) hb[0][i] = 0.0f;

    // ---- permuted weight staging ----
    auto stageW = [&](const float* Wih, const float* Whh,
                      const float* bih, const float* bhh) {
        for (int i = tid; i < GATES * 64; i += NT) {
            int row = i >> 6, k = i & 63;
            int g = row >> 6, hidx = row & 63;
            int slot = (hidx >> 1) * 8 + g * 2 + (hidx & 1);
            sW[k * GATES + slot]        = Wih[i];
            sW[(64 + k) * GATES + slot] = Whh[i];
        }
        for (int row = tid; row < GATES; row += NT) {
            int g = row >> 6, hidx = row & 63;
            sBias[(hidx >> 1) * 8 + g * 2 + (hidx & 1)] = bih[row] + bhh[row];
        }
    };
    stageW(Wih_e, Whh_e, bih_e, bhh_e);

    auto embed_to = [&](int tt, float* dst) {
        int b = tid & 63, k0 = (tid >> 6) * 8;
        float p0 = sObsF[(2 * tt) * MB + b], p1 = sObsF[(2 * tt + 1) * MB + b];
        #pragma unroll
        for (int j = 0; j < 8; j++) {
            int e = k0 + j;
            float v = fmaf(p0, sWe[e], fmaf(p1, sWe[64 + e], sBe[e]));
            dst[e * MB + b] = fmaxf(v, 0.0f);
        }
    };

    auto acc_init = [&](ULL a[4][4]) {
        #pragma unroll
        for (int g = 0; g < 4; g++) {
            ULL bp = *(const ULL*)(sBias + ty * 8 + g * 2);
            #pragma unroll
            for (int b = 0; b < 4; b++) a[g][b] = bp;
        }
    };

    // GEMM over k in [k0,k1): src = activation buffer, wsrc = weight half
    auto gemm_part = [&](const float* src, const float* wsrc,
                         ULL a[4][4], int k0, int k1) {
        const float* xp = src + k0 * MB + tx * 4;
        const float* wp = wsrc + k0 * GATES + ty * 8;
        #pragma unroll 8
        for (int k = k0; k < k1; k++) {
            float4 xv = *(const float4*)xp; xp += MB;
            ULL x0, x1, x2, x3;
            PACK_DUP(x0, __float_as_uint(xv.x));
            PACK_DUP(x1, __float_as_uint(xv.y));
            PACK_DUP(x2, __float_as_uint(xv.z));
            PACK_DUP(x3, __float_as_uint(xv.w));
            float4 w01 = *(const float4*)wp;
            float4 w23 = *(const float4*)(wp + 4); wp += GATES;
            ULL wq0 = *(ULL*)&w01.x, wq1 = *(ULL*)&w01.z;
            ULL wq2 = *(ULL*)&w23.x, wq3 = *(ULL*)&w23.z;
            FMA_F32X2(a[0][0], wq0, x0, a[0][0]);
            FMA_F32X2(a[0][1], wq0, x1, a[0][1]);
            FMA_F32X2(a[0][2], wq0, x2, a[0][2]);
            FMA_F32X2(a[0][3], wq0, x3, a[0][3]);
            FMA_F32X2(a[1][0], wq1, x0, a[1][0]);
            FMA_F32X2(a[1][1], wq1, x1, a[1][1]);
            FMA_F32X2(a[1][2], wq1, x2, a[1][2]);
            FMA_F32X2(a[1][3], wq1, x3, a[1][3]);
            FMA_F32X2(a[2][0], wq2, x0, a[2][0]);
            FMA_F32X2(a[2][1], wq2, x1, a[2][1]);
            FMA_F32X2(a[2][2], wq2, x2, a[2][2]);
            FMA_F32X2(a[2][3], wq2, x3, a[2][3]);
            FMA_F32X2(a[3][0], wq3, x0, a[3][0]);
            FMA_F32X2(a[3][1], wq3, x1, a[3][1]);
            FMA_F32X2(a[3][2], wq3, x2, a[3][2]);
            FMA_F32X2(a[3][3], wq3, x3, a[3][3]);
        }
    };

    // epilogue for one batch column b
    auto epi_col = [&](ULL a[4][4], float cS[2][4], float hv[2][4], int b) {
        unsigned i0, i1, f0, f1, g0, g1, o0, o1;
        UNPACK2(i0, i1, a[0][b]);
        UNPACK2(f0, f1, a[1][b]);
        UNPACK2(g0, g1, a[2][b]);
        UNPACK2(o0, o1, a[3][b]);
        {
            float ig = sigf(__uint_as_float(i0));
            float fg = sigf(__uint_as_float(f0));
            float gg = tanh_(__uint_as_float(g0));
            float og = sigf(__uint_as_float(o0));
            float cn = fmaf(fg, cS[0][b], ig * gg);
            cS[0][b] = cn;
            hv[0][b] = og * tanh_(cn);
        }
        {
            float ig = sigf(__uint_as_float(i1));
            float fg = sigf(__uint_as_float(f1));
            float gg = tanh_(__uint_as_float(g1));
            float og = sigf(__uint_as_float(o1));
            float cn = fmaf(fg, cS[1][b], ig * gg);
            cS[1][b] = cn;
            hv[1][b] = og * tanh_(cn);
        }
    };

    auto store_h = [&](float hv[2][4], float* hbuf) {
        *(float4*)(hbuf + (2 * ty + 0) * MB + tx * 4) =
            make_float4(hv[0][0], hv[0][1], hv[0][2], hv[0][3]);
        *(float4*)(hbuf + (2 * ty + 1) * MB + tx * 4) =
            make_float4(hv[1][0], hv[1][1], hv[1][2], hv[1][3]);
    };

    auto fc_embed = [&](const float* hbuf, int pi, float* xdst, bool emb) {
        int b = tid & 63;
        float p0 = sBfc[0], p1 = sBfc[1];
        const float* hcol = hbuf + b;
        #pragma unroll 8
        for (int r = 0; r < 64; r++) {
            float h = hcol[r * MB];
            p0 = fmaf(h, sWfc[r],      p0);
            p1 = fmaf(h, sWfc[64 + r], p1);
        }
        if (tid < MB) {
            size_t o = ((size_t)(b0 + b) * pred_len + pi) * 2;
            *(float2*)(out + o) = make_float2(p0, p1);
        }
        if (emb) {
            int k0 = (tid >> 6) * 8;
            #pragma unroll
            for (int j = 0; j < 8; j++) {
                int e = k0 + j;
                float v = fmaf(p0, sWe[e], fmaf(p1, sWe[64 + e], sBe[e]));
                xdst[e * MB + b] = fmaxf(v, 0.0f);
            }
        }
    };

    // ---- prologue: x_0, x_1 embedded; acc = bias + Wih_e . x_0 ----
    embed_to(0, xb[0]);
    embed_to(1, xb[1]);
    __syncthreads();

    ULL acc[4][4], accN[4][4];
    acc_init(acc);
    gemm_part(xb[0], sW, acc, 0, 64);
    __syncthreads();

    float c[2][4] = {{0.f,0.f,0.f,0.f},{0.f,0.f,0.f,0.f}};

    const int TOT = OBS_ + pred_len;
    for (int t = 0; t < TOT; t++) {
        const int cur = t & 1, nxt = cur ^ 1;
        if (t < OBS_) {
            // h-part of this step's gates
            gemm_part(hb[cur], sW + 64 * GATES, acc, 0, 64);
            float hv[2][4];
            if (t < OBS_ - 1) {
                // interleaved: epilogue (MUFU) + next-step x-GEMM (FFMA2)
                acc_init(accN);
                epi_col(acc, c, hv, 0);
                epi_col(acc, c, hv, 1);
                gemm_part(xb[nxt], sW, accN, 0, 32);
                epi_col(acc, c, hv, 2);
                epi_col(acc, c, hv, 3);
                gemm_part(xb[nxt], sW, accN, 32, 64);
                store_h(hv, hb[nxt]);
                if (t + 2 < OBS_) embed_to(t + 2, xb[cur]);
                __syncthreads();
                #pragma unroll
                for (int g = 0; g < 4; g++)
                    #pragma unroll
                    for (int b = 0; b < 4; b++) acc[g][b] = accN[g][b];
            } else {
                epi_col(acc, c, hv, 0);
                epi_col(acc, c, hv, 1);
                epi_col(acc, c, hv, 2);
                epi_col(acc, c, hv, 3);
                store_h(hv, hb[nxt]);
                __syncthreads();
            }
        } else {
            if (t == OBS_) { stageW(Wih_d, Whh_d, bih_d, bhh_d); __syncthreads(); }
            acc_init(acc);
            gemm_part(xb[nxt], sW, acc, 0, 64);             // x_t
            gemm_part(hb[cur], sW + 64 * GATES, acc, 0, 64); // h_{t-1}
            float hv[2][4];
            epi_col(acc, c, hv, 0);
            epi_col(acc, c, hv, 1);
            epi_col(acc, c, hv, 2);
            epi_col(acc, c, hv, 3);
            store_h(hv, hb[nxt]);
            __syncthreads();
            fc_embed(hb[nxt], t - OBS_, xb[cur], t != TOT - 1);
            __syncthreads();
        }
    }
}

extern "C" void kernel_launch(void* const* d_in, const int* in_sizes, int n_in,
                              void* d_out, int out_size)
{
    const float* obs   = (const float*)d_in[0];
    const float* W_emb = (const float*)d_in[1];
    const float* b_emb = (const float*)d_in[2];
    const float* Wih_e = (const float*)d_in[3];
    const float* Whh_e = (const float*)d_in[4];
    const float* bih_e = (const float*)d_in[5];
    const float* bhh_e = (const float*)d_in[6];
    const float* Wih_d = (const float*)d_in[7];
    const float* Whh_d = (const float*)d_in[8];
    const float* bih_d = (const float*)d_in[9];
    const float* bhh_d = (const float*)d_in[10];
    const float* W_fc  = (const float*)d_in[11];
    const float* b_fc  = (const float*)d_in[12];
    float* out = (float*)d_out;

    int B = in_sizes[0] / (OBS_ * 2);
    int pred_len = out_size / (B * 2);

    cudaFuncSetAttribute(vanilla_lstm_kernel,
                         cudaFuncAttributeMaxDynamicSharedMemorySize, SMEM_BYTES);

    int grid = B / MB;
    vanilla_lstm_kernel<<<grid, NT, SMEM_BYTES>>>(
        obs, W_emb, b_emb, Wih_e, Whh_e, bih_e, bhh_e,
        Wih_d, Whh_d, bih_d, bhh_d, W_fc, b_fc, out, pred_len);
}

// round 10
// speedup vs baseline: 1.2832x; 1.0727x over previous
#include <cuda_runtime.h>
#include <math.h>
#include <cstdint>

#define GATES 256
#define OBS_  20
#define MB    64
#define NT    512
#define NW    16

typedef unsigned long long ULL;

// ---- SMEM layout (floats) ----
#define OFF_W    0                     // [128][256] swizzled (see stageW)
#define OFF_BIAS (OFF_W + 128*256)     // [256] permuted logical
#define OFF_WE   (OFF_BIAS + 256)      // [2][64]
#define OFF_BE   (OFF_WE + 128)        // [64]
#define OFF_WFC  (OFF_BE + 64)         // [2][64]
#define OFF_BFC  (OFF_WFC + 128)       // [2]+pad
#define OFF_X    (OFF_BFC + 4)         // NW * [64][4]
#define OFF_H    (OFF_X + NW*256)      // NW * [64][4]
#define OFF_OBS  (OFF_H + NW*256)      // NW * [40][4]
#define SMEM_FLOATS (OFF_OBS + NW*160)
#define SMEM_BYTES  (SMEM_FLOATS * 4)

#define FMA_F32X2(d, a, b, c_) \
    asm("fma.rn.f32x2 %0, %1, %2, %3;" : "=l"(d) : "l"(a), "l"(b), "l"(c_))
#define PACK_DUP(out, v) \
    asm("mov.b64 %0, {%1, %1};" : "=l"(out) : "r"(v))
#define UNPACK2(lo, hi, in) \
    asm("mov.b64 {%0, %1}, %2;" : "=r"(lo), "=r"(hi) : "l"(in))

__device__ __forceinline__ float sigf(float x) {
    return __fdividef(1.0f, 1.0f + __expf(-x));
}
__device__ __forceinline__ float tanh_(float x) {
    float a = fabsf(x);
    float e = __expf(2.0f * a);
    float t = 1.0f - __fdividef(2.0f, e + 1.0f);
    return copysignf(t, x);
}

__global__ void __launch_bounds__(NT, 1)
vanilla_lstm_kernel(const float* __restrict__ obs,
                    const float* __restrict__ W_emb,  const float* __restrict__ b_emb,
                    const float* __restrict__ Wih_e,  const float* __restrict__ Whh_e,
                    const float* __restrict__ bih_e,  const float* __restrict__ bhh_e,
                    const float* __restrict__ Wih_d,  const float* __restrict__ Whh_d,
                    const float* __restrict__ bih_d,  const float* __restrict__ bhh_d,
                    const float* __restrict__ W_fc,   const float* __restrict__ b_fc,
                    float* __restrict__ out, int pred_len)
{
    extern __shared__ float sm[];
    float* sW    = sm + OFF_W;
    float* sBias = sm + OFF_BIAS;
    float* sWe   = sm + OFF_WE;
    float* sBe   = sm + OFF_BE;
    float* sWfc  = sm + OFF_WFC;
    float* sBfc  = sm + OFF_BFC;

    const int tid  = threadIdx.x;
    const int lane = tid & 31;
    const int w    = tid >> 5;
    const int b0   = blockIdx.x * MB;

    // per-warp strips
    float4* xW4 = (float4*)(sm + OFF_X) + w * 64;
    float4* hW4 = (float4*)(sm + OFF_H) + w * 64;
    float*  oW  = sm + OFF_OBS + w * 160;

    // ---- stage small params ----
    if (tid < 128) sWe[tid] = W_emb[(tid & 63) * 2 + (tid >> 6)];
    if (tid < 64)  sBe[tid] = b_emb[tid];
    if (tid < 128) sWfc[tid] = W_fc[tid];
    if (tid < 2)   sBfc[tid] = b_fc[tid];

    // obs: sObsW[w][t*2+p][c]  (coalesced global read)
    for (int i = tid; i < MB * 40; i += NT) {
        int b = i / 40, r = i % 40;
        sm[OFF_OBS + (b >> 2) * 160 + r * 4 + (b & 3)] =
            obs[(size_t)(b0 + b) * 40 + r];
    }

    // ---- weight staging, lane-swizzled so both LDS.128 are conflict-free ----
    // logical: lane l owns gate slots l*8+g*2+d (g=gate, d=hidden low bit)
    // physical 16B slot for (l, half=g>>1): 2l + (half ^ ((l>>2)&1))
    auto stageW = [&](const float* Wih, const float* Whh,
                      const float* bih, const float* bhh) {
        for (int i = tid; i < GATES * 64; i += NT) {
            int row = i >> 6, k = i & 63;
            int g = row >> 6, rem = row & 63;
            int l = rem >> 1, d = rem & 1;
            int swz = (l >> 2) & 1;
            int phys = (2 * l + ((g >> 1) ^ swz)) * 4 + (g & 1) * 2 + d;
            sW[k * GATES + phys]        = Wih[i];
            sW[(64 + k) * GATES + phys] = Whh[i];
        }
        for (int row = tid; row < GATES; row += NT) {
            int g = row >> 6, rem = row & 63;
            sBias[(rem >> 1) * 8 + g * 2 + (rem & 1)] = bih[row] + bhh[row];
        }
    };
    stageW(Wih_e, Whh_e, bih_e, bhh_e);
    __syncthreads();

    // ---- per-lane hoisted constants ----
    const int swz = (lane >> 2) & 1;
    const char* wAx = (const char*)sW + (2 * lane + swz) * 16;       // half0: g0,g1
    const char* wBx = (const char*)sW + (2 * lane + 1 - swz) * 16;   // half1: g2,g3
    const char* wAh = wAx + 64 * 1024;
    const char* wBh = wBx + 64 * 1024;

    const int e0 = 2 * lane, e1 = 2 * lane + 1;
    float we00 = sWe[e0], we01 = sWe[64 + e0], be0 = sBe[e0];
    float we10 = sWe[e1], we11 = sWe[64 + e1], be1 = sBe[e1];
    float wfc00 = sWfc[e0], wfc01 = sWfc[e1];
    float wfc10 = sWfc[64 + e0], wfc11 = sWfc[64 + e1];
    float bfc0 = sBfc[0], bfc1 = sBfc[1];

    ULL biasv[4];
    #pragma unroll
    for (int g = 0; g < 4; g++)
        biasv[g] = *(const ULL*)(sBias + lane * 8 + g * 2);

    // zero h strip
    hW4[2 * lane]     = make_float4(0.f, 0.f, 0.f, 0.f);
    hW4[2 * lane + 1] = make_float4(0.f, 0.f, 0.f, 0.f);

    // embed from (p0[4], p1[4]) into register rows e0, e1
    float4 xe0, xe1;
    auto embed_regs = [&](float4 P0, float4 P1) {
        const float* p0 = &P0.x; const float* p1 = &P1.x;
        float* a = &xe0.x; float* b = &xe1.x;
        #pragma unroll
        for (int j = 0; j < 4; j++) {
            a[j] = fmaxf(fmaf(p0[j], we00, fmaf(p1[j], we01, be0)), 0.f);
            b[j] = fmaxf(fmaf(p0[j], we10, fmaf(p1[j], we11, be1)), 0.f);
        }
    };
    auto embed_obs = [&](int tt) {
        float4 P0 = *(const float4*)(oW + tt * 8);
        float4 P1 = *(const float4*)(oW + tt * 8 + 4);
        embed_regs(P0, P1);
    };

    // 64-k GEMM half: xsrc broadcast rows, weights via swizzled pointers
    auto gemm64 = [&](const float4* xsrc, const char* wA, const char* wB,
                      ULL a[4][4]) {
        #pragma unroll 8
        for (int k = 0; k < 64; k++) {
            float4 xv = xsrc[k];
            ULL x0, x1, x2, x3;
            PACK_DUP(x0, __float_as_uint(xv.x));
            PACK_DUP(x1, __float_as_uint(xv.y));
            PACK_DUP(x2, __float_as_uint(xv.z));
            PACK_DUP(x3, __float_as_uint(xv.w));
            float4 w01 = *(const float4*)(wA + k * 1024);
            float4 w23 = *(const float4*)(wB + k * 1024);
            ULL wq0 = *(ULL*)&w01.x, wq1 = *(ULL*)&w01.z;
            ULL wq2 = *(ULL*)&w23.x, wq3 = *(ULL*)&w23.z;
            FMA_F32X2(a[0][0], wq0, x0, a[0][0]);
            FMA_F32X2(a[0][1], wq0, x1, a[0][1]);
            FMA_F32X2(a[0][2], wq0, x2, a[0][2]);
            FMA_F32X2(a[0][3], wq0, x3, a[0][3]);
            FMA_F32X2(a[1][0], wq1, x0, a[1][0]);
            FMA_F32X2(a[1][1], wq1, x1, a[1][1]);
            FMA_F32X2(a[1][2], wq1, x2, a[1][2]);
            FMA_F32X2(a[1][3], wq1, x3, a[1][3]);
            FMA_F32X2(a[2][0], wq2, x0, a[2][0]);
            FMA_F32X2(a[2][1], wq2, x1, a[2][1]);
            FMA_F32X2(a[2][2], wq2, x2, a[2][2]);
            FMA_F32X2(a[2][3], wq2, x3, a[2][3]);
            FMA_F32X2(a[3][0], wq3, x0, a[3][0]);
            FMA_F32X2(a[3][1], wq3, x1, a[3][1]);
            FMA_F32X2(a[3][2], wq3, x2, a[3][2]);
            FMA_F32X2(a[3][3], wq3, x3, a[3][3]);
        }
    };

    float c[2][4] = {{0.f,0.f,0.f,0.f},{0.f,0.f,0.f,0.f}};
    float hv[2][4];

    auto epi_col = [&](ULL a[4][4], int b) {
        unsigned i0, i1, f0, f1, g0, g1, o0, o1;
        UNPACK2(i0, i1, a[0][b]);
        UNPACK2(f0, f1, a[1][b]);
        UNPACK2(g0, g1, a[2][b]);
        UNPACK2(o0, o1, a[3][b]);
        {
            float ig = sigf(__uint_as_float(i0));
            float fg = sigf(__uint_as_float(f0));
            float gg = tanh_(__uint_as_float(g0));
            float og = sigf(__uint_as_float(o0));
            float cn = fmaf(fg, c[0][b], ig * gg);
            c[0][b] = cn;
            hv[0][b] = og * tanh_(cn);
        }
        {
            float ig = sigf(__uint_as_float(i1));
            float fg = sigf(__uint_as_float(f1));
            float gg = tanh_(__uint_as_float(g1));
            float og = sigf(__uint_as_float(o1));
            float cn = fmaf(fg, c[1][b], ig * gg);
            c[1][b] = cn;
            hv[1][b] = og * tanh_(cn);
        }
    };

    // ---- prologue: x_0 ----
    embed_obs(0);
    xW4[2 * lane]     = xe0;
    xW4[2 * lane + 1] = xe1;
    __syncwarp();

    const int TOT = OBS_ + pred_len;
    for (int t = 0; t < TOT; t++) {
        if (t == OBS_) {                 // enc -> dec weight swap (only global syncs)
            __syncthreads();
            stageW(Wih_d, Whh_d, bih_d, bhh_d);
            __syncthreads();
            #pragma unroll
            for (int g = 0; g < 4; g++)
                biasv[g] = *(const ULL*)(sBias + lane * 8 + g * 2);
        }

        ULL acc[4][4];
        #pragma unroll
        for (int g = 0; g < 4; g++)
            #pragma unroll
            for (int b = 0; b < 4; b++) acc[g][b] = biasv[g];

        gemm64(xW4, wAx, wBx, acc);      // x part
        gemm64(hW4, wAh, wBh, acc);      // h part

        bool do_embed = false;
        if (t < OBS_ - 1) { embed_obs(t + 1); do_embed = true; }

        epi_col(acc, 0);
        epi_col(acc, 1);
        epi_col(acc, 2);
        epi_col(acc, 3);

        if (t >= OBS_) {
            // FC: warp butterfly reduction over 64 hidden
            float r[8];
            #pragma unroll
            for (int b = 0; b < 4; b++) {
                r[b]     = fmaf(hv[0][b], wfc00, hv[1][b] * wfc01);
                r[4 + b] = fmaf(hv[0][b], wfc10, hv[1][b] * wfc11);
            }
            #pragma unroll
            for (int off = 16; off >= 1; off >>= 1)
                #pragma unroll
                for (int j = 0; j < 8; j++)
                    r[j] += __shfl_xor_sync(0xffffffffu, r[j], off);
            float p0[4], p1[4];
            #pragma unroll
            for (int b = 0; b < 4; b++) { p0[b] = r[b] + bfc0; p1[b] = r[4 + b] + bfc1; }

            if (lane < 4) {
                size_t o = ((size_t)(b0 + w * 4 + lane) * pred_len + (t - OBS_)) * 2;
                *(float2*)(out + o) = make_float2(p0[lane], p1[lane]);
            }
            if (t < TOT - 1) {
                embed_regs(make_float4(p0[0], p0[1], p0[2], p0[3]),
                           make_float4(p1[0], p1[1], p1[2], p1[3]));
                do_embed = true;
            }
        }

        __syncwarp();                    // all lanes done reading x/h strips
        if (t < TOT - 1) {
            hW4[2 * lane]     = make_float4(hv[0][0], hv[0][1], hv[0][2], hv[0][3]);
            hW4[2 * lane + 1] = make_float4(hv[1][0], hv[1][1], hv[1][2], hv[1][3]);
        }
        if (do_embed) {                  // t==OBS_-1 keeps x = emb(obs[19])
            xW4[2 * lane]     = xe0;
            xW4[2 * lane + 1] = xe1;
        }
        __syncwarp();
    }
}

extern "C" void kernel_launch(void* const* d_in, const int* in_sizes, int n_in,
                              void* d_out, int out_size)
{
    const float* obs   = (const float*)d_in[0];
    const float* W_emb = (const float*)d_in[1];
    const float* b_emb = (const float*)d_in[2];
    const float* Wih_e = (const float*)d_in[3];
    const float* Whh_e = (const float*)d_in[4];
    const float* bih_e = (const float*)d_in[5];
    const float* bhh_e = (const float*)d_in[6];
    const float* Wih_d = (const float*)d_in[7];
    const float* Whh_d = (const float*)d_in[8];
    const float* bih_d = (const float*)d_in[9];
    const float* bhh_d = (const float*)d_in[10];
    const float* W_fc  = (const float*)d_in[11];
    const float* b_fc  = (const float*)d_in[12];
    float* out = (float*)d_out;

    int B = in_sizes[0] / (OBS_ * 2);
    int pred_len = out_size / (B * 2);

    cudaFuncSetAttribute(vanilla_lstm_kernel,
                         cudaFuncAttributeMaxDynamicSharedMemorySize, SMEM_BYTES);

    int grid = B / MB;
    vanilla_lstm_kernel<<<grid, NT, SMEM_BYTES>>>(
        obs, W_emb, b_emb, Wih_e, Whh_e, bih_e, bhh_e,
        Wih_d, Whh_d, bih_d, bhh_d, W_fc, b_fc, out, pred_len);
}